// round 16
// baseline (speedup 1.0000x reference)
#include <cuda_runtime.h>
#include <cuda_bf16.h>
#include <cstdint>

// ---------------------------------------------------------------------------
// Problem constants
// ---------------------------------------------------------------------------
#define N_TOK    8192
#define M_DIM    2048
#define E_NUM    8
#define H_DIM    8192
#define C_CAP    1024
#define EC_SLOTS 8192

// GEMM tiling: block 128x64, 8 warps (4m x 2n), warp tile 32x32, K-chunk 32
// 2 CTAs per SM (92KB smem, 256 threads each) to cover barrier tails.
#define KCHUNK   32
#define ROW_STRIDE_B  80                     // 32 bf16 (64B) + 16B pad
#define A_SPLIT  (128 * ROW_STRIDE_B)        // 10240
#define B_SPLIT  (64 * ROW_STRIDE_B)         // 5120
#define OFF_AH   0
#define OFF_AL   A_SPLIT
#define OFF_BH   (2 * A_SPLIT)
#define OFF_BL   (2 * A_SPLIT + B_SPLIT)
#define STAGE_B  (2 * A_SPLIT + 2 * B_SPLIT) // 30720
#define NSTAGE   3
#define SMEM_BYTES (NSTAGE * STAGE_B)        // 92160
#define NTHREADS 256

// ---------------------------------------------------------------------------
// Scratch (device globals; no dynamic allocation allowed)
// ---------------------------------------------------------------------------
__device__ int   g_idx  [N_TOK];
__device__ float g_gate1[N_TOK];
__device__ float g_gates[N_TOK * E_NUM];
__device__ int   g_s2t  [EC_SLOTS];

__device__ __nv_bfloat16 g_disp_hi[(size_t)EC_SLOTS * M_DIM];
__device__ __nv_bfloat16 g_disp_lo[(size_t)EC_SLOTS * M_DIM];
__device__ __nv_bfloat16 g_h_hi   [(size_t)EC_SLOTS * H_DIM];
__device__ __nv_bfloat16 g_h_lo   [(size_t)EC_SLOTS * H_DIM];
// transposed bf16 weight splits: w1T [E][H][M], w2T [E][M][H]  (K contiguous)
__device__ __nv_bfloat16 g_w1t_hi[(size_t)E_NUM * H_DIM * M_DIM];
__device__ __nv_bfloat16 g_w1t_lo[(size_t)E_NUM * H_DIM * M_DIM];
__device__ __nv_bfloat16 g_w2t_hi[(size_t)E_NUM * M_DIM * H_DIM];
__device__ __nv_bfloat16 g_w2t_lo[(size_t)E_NUM * M_DIM * H_DIM];

// ---------------------------------------------------------------------------
// helpers
// ---------------------------------------------------------------------------
__device__ __forceinline__ uint32_t s2u(const void* p) {
    return (uint32_t)__cvta_generic_to_shared(p);
}
__device__ __forceinline__ void cp16(uint32_t s, const void* g) {
    asm volatile("cp.async.cg.shared.global [%0], [%1], 16;" :: "r"(s), "l"(g));
}
__device__ __forceinline__ void ldsm4(uint32_t* r, uint32_t a) {
    asm volatile("ldmatrix.sync.aligned.m8n8.x4.shared.b16 {%0,%1,%2,%3}, [%4];"
                 : "=r"(r[0]), "=r"(r[1]), "=r"(r[2]), "=r"(r[3]) : "r"(a));
}
__device__ __forceinline__ void ldsm2(uint32_t* r, uint32_t a) {
    asm volatile("ldmatrix.sync.aligned.m8n8.x2.shared.b16 {%0,%1}, [%2];"
                 : "=r"(r[0]), "=r"(r[1]) : "r"(a));
}
__device__ __forceinline__ void mmabf16(float* d, const uint32_t* a, const uint32_t* b) {
    asm volatile("mma.sync.aligned.m16n8k16.row.col.f32.bf16.bf16.f32 "
                 "{%0,%1,%2,%3}, {%4,%5,%6,%7}, {%8,%9}, {%0,%1,%2,%3};"
                 : "+f"(d[0]), "+f"(d[1]), "+f"(d[2]), "+f"(d[3])
                 : "r"(a[0]), "r"(a[1]), "r"(a[2]), "r"(a[3]),
                   "r"(b[0]), "r"(b[1]));
}
__device__ __forceinline__ void bsplit(float f, __nv_bfloat16& hi, __nv_bfloat16& lo)
{
    hi = __float2bfloat16(f);
    lo = __float2bfloat16(f - __bfloat162float(hi));
}

// ---------------------------------------------------------------------------
// init: slot table to -1, zero output
// ---------------------------------------------------------------------------
__global__ void init_kernel(float* __restrict__ out)
{
    int tid = blockIdx.x * blockDim.x + threadIdx.x;
    if (tid < EC_SLOTS) g_s2t[tid] = -1;
    float4* o4 = (float4*)out;
    const int n4 = (N_TOK * M_DIM) / 4;
    const int stride = gridDim.x * blockDim.x;
    for (int i = tid; i < n4; i += stride)
        o4[i] = make_float4(0.f, 0.f, 0.f, 0.f);
}

// ---------------------------------------------------------------------------
// gate: exact fp32 routing
// ---------------------------------------------------------------------------
__global__ __launch_bounds__(256) void gate_kernel(
    const float* __restrict__ x, const float* __restrict__ wg)
{
    __shared__ float sx[M_DIM];
    __shared__ float slog[E_NUM];

    const int tok = blockIdx.x;
    const int tid = threadIdx.x;

    const float4* xr = (const float4*)(x + (size_t)tok * M_DIM);
    float4* sx4 = (float4*)sx;
    for (int i = tid; i < M_DIM / 4; i += 256) sx4[i] = xr[i];
    __syncthreads();

    const int wid = tid >> 5, lane = tid & 31;
    const float* __restrict__ w = wg + wid * M_DIM;
    float sum = 0.f;
    for (int m = lane; m < M_DIM; m += 32) sum = fmaf(sx[m], w[m], sum);
#pragma unroll
    for (int o = 16; o; o >>= 1) sum += __shfl_xor_sync(0xffffffffu, sum, o);
    if (lane == 0) slog[wid] = sum;
    __syncthreads();

    if (tid == 0) {
        float mx = slog[0]; int am = 0;
#pragma unroll
        for (int e = 1; e < E_NUM; ++e)
            if (slog[e] > mx) { mx = slog[e]; am = e; }
        float ge[E_NUM], den = 0.f;
#pragma unroll
        for (int e = 0; e < E_NUM; ++e) { ge[e] = expf(slog[e] - mx); den += ge[e]; }
        const float inv = 1.f / den;
#pragma unroll
        for (int e = 0; e < E_NUM; ++e) g_gates[tok * E_NUM + e] = ge[e] * inv;
        g_idx[tok]   = am;
        g_gate1[tok] = ge[am] * inv;
    }
}

// ---------------------------------------------------------------------------
// sched: exact cumsum capacity assignment + l_aux
// ---------------------------------------------------------------------------
__global__ __launch_bounds__(256) void sched_kernel(float* __restrict__ out,
                                                    int write_laux)
{
    __shared__ int   s_ce[E_NUM];
    __shared__ float s_me[E_NUM];

    const int tid = threadIdx.x;
    const int wid = tid >> 5, lane = tid & 31;

    int count = 0;
    for (int base = 0; base < N_TOK; base += 32) {
        const int tok = base + lane;
        const bool mine = (g_idx[tok] == wid);
        const unsigned bal = __ballot_sync(0xffffffffu, mine);
        if (mine) {
            const int loc = count + __popc(bal & ((1u << lane) - 1u));
            if (loc < C_CAP) g_s2t[wid * C_CAP + loc] = tok;
        }
        count += __popc(bal);
    }
    if (lane == 0) s_ce[wid] = count;

    float me = 0.f;
    for (int t = lane; t < N_TOK; t += 32) me += g_gates[t * E_NUM + wid];
#pragma unroll
    for (int o = 16; o; o >>= 1) me += __shfl_xor_sync(0xffffffffu, me, o);
    if (lane == 0) s_me[wid] = me;
    __syncthreads();

    if (tid == 0 && write_laux) {
        float acc = 0.f;
#pragma unroll
        for (int e = 0; e < E_NUM; ++e) acc += s_me[e] * (float)s_ce[e];
        out[(size_t)N_TOK * M_DIM] =
            acc * ((float)E_NUM / ((float)N_TOK * (float)N_TOK));
    }
}

// ---------------------------------------------------------------------------
// disp: gather token rows into slot order, split fp32 -> bf16 hi/lo
// ---------------------------------------------------------------------------
__global__ __launch_bounds__(256) void disp_kernel(const float* __restrict__ x)
{
    const int slot = blockIdx.x;
    const int t = g_s2t[slot];
    const float4* src = (t >= 0) ? (const float4*)(x + (size_t)t * M_DIM) : nullptr;
    __nv_bfloat16* dh = g_disp_hi + (size_t)slot * M_DIM;
    __nv_bfloat16* dl = g_disp_lo + (size_t)slot * M_DIM;
    for (int i = threadIdx.x; i < M_DIM / 4; i += 256) {
        float4 v = src ? src[i] : make_float4(0.f, 0.f, 0.f, 0.f);
        __nv_bfloat16 hh[4], ll[4];
        bsplit(v.x, hh[0], ll[0]); bsplit(v.y, hh[1], ll[1]);
        bsplit(v.z, hh[2], ll[2]); bsplit(v.w, hh[3], ll[3]);
        *(uint2*)(dh + i * 4) = *(uint2*)hh;
        *(uint2*)(dl + i * 4) = *(uint2*)ll;
    }
}

// ---------------------------------------------------------------------------
// wsplit v2: 64x64 tiles, vectorized, amortized index math
// ---------------------------------------------------------------------------
__global__ __launch_bounds__(512) void wsplit_kernel(
    const float* __restrict__ src,
    __nv_bfloat16* __restrict__ dhi,
    __nv_bfloat16* __restrict__ dlo,
    int R, int C)
{
    __shared__ float tile[64][65];
    const int e  = blockIdx.z;
    const int c0 = blockIdx.x * 64;
    const int r0 = blockIdx.y * 64;
    const int tid = threadIdx.x;

    const float* s = src + (size_t)e * R * C;
#pragma unroll
    for (int i = 0; i < 2; ++i) {
        const int u = tid + i * 512;
        const int row = u >> 4, q = u & 15;
        float4 v = *(const float4*)(s + (size_t)(r0 + row) * C + c0 + q * 4);
        tile[row][q * 4 + 0] = v.x;
        tile[row][q * 4 + 1] = v.y;
        tile[row][q * 4 + 2] = v.z;
        tile[row][q * 4 + 3] = v.w;
    }
    __syncthreads();

    const int c  = tid >> 3;
    const int rg = tid & 7;
    __nv_bfloat16 hh[8], ll[8];
#pragma unroll
    for (int j = 0; j < 8; ++j)
        bsplit(tile[rg * 8 + j][c], hh[j], ll[j]);
    const size_t o = (size_t)e * C * R + (size_t)(c0 + c) * R + r0 + rg * 8;
    *(uint4*)(dhi + o) = *(uint4*)hh;
    *(uint4*)(dlo + o) = *(uint4*)ll;
}

// ---------------------------------------------------------------------------
// HMMA mainloop: block 128x64, 8 warps, 3-term bf16 split, 3-stage pipeline
// ---------------------------------------------------------------------------
__device__ __forceinline__ void hmma_mainloop(
    const char* __restrict__ Ah, const char* __restrict__ Al,
    const char* __restrict__ Bh, const char* __restrict__ Bl,
    size_t pitch, int chunks, char* smem, float acc[2][4][4])
{
    const int tid  = threadIdx.x;
    const int wid  = tid >> 5, lane = tid & 31;
    const int wm   = (wid & 3) * 32;
    const int wn   = (wid >> 2) * 32;
    const uint32_t sbase = s2u(smem);

    // loader: A planes 512 units each (2 consecutive segs/thread), B 1/thread
    const int arow = tid >> 1;                           // 0..127
    const int aseg2 = (tid & 1) * 2;                     // first seg 0 or 2
    const uint32_t aso = arow * ROW_STRIDE_B + aseg2 * 16;
    const size_t   ago = (size_t)arow * pitch + aseg2 * 16;
    const int brow = tid >> 2, bseg = tid & 3;           // 0..63, 0..3
    const uint32_t bso = brow * ROW_STRIDE_B + bseg * 16;
    const size_t   bgo = (size_t)brow * pitch + bseg * 16;

    auto load_stage = [&](int st, int c) {
        const uint32_t sb = sbase + st * STAGE_B;
        const size_t kb = (size_t)c * (KCHUNK * 2);
        cp16(sb + OFF_AH + aso,      Ah + ago + kb);
        cp16(sb + OFF_AH + aso + 16, Ah + ago + kb + 16);
        cp16(sb + OFF_AL + aso,      Al + ago + kb);
        cp16(sb + OFF_AL + aso + 16, Al + ago + kb + 16);
        cp16(sb + OFF_BH + bso,      Bh + bgo + kb);
        cp16(sb + OFF_BL + bso,      Bl + bgo + kb);
        asm volatile("cp.async.commit_group;");
    };

#pragma unroll
    for (int s = 0; s < NSTAGE - 1; ++s) load_stage(s, s);

    const uint32_t aoff = (uint32_t)((wm + (lane & 15)) * ROW_STRIDE_B
                                     + ((lane >> 4) & 1) * 16);
    const uint32_t boff = (uint32_t)((wn + (lane & 7)) * ROW_STRIDE_B
                                     + ((lane >> 3) & 1) * 16);

    int buf = 0;
#pragma unroll 1
    for (int c = 0; c < chunks; ++c) {
        asm volatile("cp.async.wait_group %0;" :: "n"(NSTAGE - 2) : "memory");
        __syncthreads();

        if (c + NSTAGE - 1 < chunks)
            load_stage((c + NSTAGE - 1) % NSTAGE, c + NSTAGE - 1);

        const uint32_t sb = sbase + buf * STAGE_B;
#pragma unroll
        for (int ks = 0; ks < 2; ++ks) {
            const int kb2 = ks * 32;
            uint32_t ah[2][4], al[2][4], bh[4][2], bl[4][2];
#pragma unroll
            for (int mi = 0; mi < 2; ++mi) {
                const uint32_t ad = sb + aoff + kb2 + mi * 16 * ROW_STRIDE_B;
                ldsm4(ah[mi], ad + OFF_AH);
                ldsm4(al[mi], ad + OFF_AL);
            }
#pragma unroll
            for (int ni = 0; ni < 4; ++ni) {
                const uint32_t bd = sb + boff + kb2 + ni * 8 * ROW_STRIDE_B;
                ldsm2(bh[ni], bd + OFF_BH);
                ldsm2(bl[ni], bd + OFF_BL);
            }
#pragma unroll
            for (int mi = 0; mi < 2; ++mi)
#pragma unroll
                for (int ni = 0; ni < 4; ++ni)
                    mmabf16(acc[mi][ni], ah[mi], bh[ni]);
#pragma unroll
            for (int mi = 0; mi < 2; ++mi)
#pragma unroll
                for (int ni = 0; ni < 4; ++ni)
                    mmabf16(acc[mi][ni], al[mi], bh[ni]);
#pragma unroll
            for (int mi = 0; mi < 2; ++mi)
#pragma unroll
                for (int ni = 0; ni < 4; ++ni)
                    mmabf16(acc[mi][ni], ah[mi], bl[ni]);
        }
        buf = (buf + 1 == NSTAGE) ? 0 : buf + 1;
    }
}

// ---------------------------------------------------------------------------
// GEMM1: h[slot] = relu( disp[slot] @ w1[e]^T(cols) + b1[e] ) -> split hi/lo
// ---------------------------------------------------------------------------
__global__ __launch_bounds__(NTHREADS, 2) void gemm1_mma(const float* __restrict__ b1)
{
    extern __shared__ char smem[];
    const int tid = threadIdx.x;
    const int wid = tid >> 5, lane = tid & 31;
    const int row0 = blockIdx.y * 128;
    const int col0 = blockIdx.x * 64;
    const int e    = row0 >> 10;

    float acc[2][4][4];
#pragma unroll
    for (int mi = 0; mi < 2; ++mi)
#pragma unroll
        for (int ni = 0; ni < 4; ++ni)
#pragma unroll
            for (int k = 0; k < 4; ++k) acc[mi][ni][k] = 0.f;

    hmma_mainloop(
        (const char*)(g_disp_hi + (size_t)row0 * M_DIM),
        (const char*)(g_disp_lo + (size_t)row0 * M_DIM),
        (const char*)(g_w1t_hi + (size_t)e * H_DIM * M_DIM + (size_t)col0 * M_DIM),
        (const char*)(g_w1t_lo + (size_t)e * H_DIM * M_DIM + (size_t)col0 * M_DIM),
        (size_t)M_DIM * 2, M_DIM / KCHUNK, smem, acc);

    const int wm = (wid & 3) * 32;
    const int wn = (wid >> 2) * 32;
    const float* b1g = b1 + (size_t)e * H_DIM;

#pragma unroll
    for (int ni = 0; ni < 4; ++ni) {
        const int cg = col0 + wn + ni * 8 + (lane & 3) * 2;
        const float bv0 = b1g[cg], bv1 = b1g[cg + 1];
#pragma unroll
        for (int mi = 0; mi < 2; ++mi)
#pragma unroll
            for (int h = 0; h < 2; ++h) {
                const int rg = row0 + wm + mi * 16 + (lane >> 2) + h * 8;
                float v0 = fmaxf(acc[mi][ni][h * 2 + 0] + bv0, 0.f);
                float v1 = fmaxf(acc[mi][ni][h * 2 + 1] + bv1, 0.f);
                __nv_bfloat16 h0, l0, h1, l1;
                bsplit(v0, h0, l0);
                bsplit(v1, h1, l1);
                *(__nv_bfloat162*)(g_h_hi + (size_t)rg * H_DIM + cg) =
                    __nv_bfloat162(h0, h1);
                *(__nv_bfloat162*)(g_h_lo + (size_t)rg * H_DIM + cg) =
                    __nv_bfloat162(l0, l1);
            }
    }
}

// ---------------------------------------------------------------------------
// GEMM2: out[token(slot)] = gate1 * ( h[slot] @ w2[e]^T(cols) + b2[e] )
// ---------------------------------------------------------------------------
__global__ __launch_bounds__(NTHREADS, 2) void gemm2_mma(const float* __restrict__ b2,
                                                         float* __restrict__ out)
{
    extern __shared__ char smem[];
    const int tid = threadIdx.x;
    const int wid = tid >> 5, lane = tid & 31;
    const int row0 = blockIdx.y * 128;
    const int col0 = blockIdx.x * 64;
    const int e    = row0 >> 10;

    float acc[2][4][4];
#pragma unroll
    for (int mi = 0; mi < 2; ++mi)
#pragma unroll
        for (int ni = 0; ni < 4; ++ni)
#pragma unroll
            for (int k = 0; k < 4; ++k) acc[mi][ni][k] = 0.f;

    hmma_mainloop(
        (const char*)(g_h_hi + (size_t)row0 * H_DIM),
        (const char*)(g_h_lo + (size_t)row0 * H_DIM),
        (const char*)(g_w2t_hi + (size_t)e * M_DIM * H_DIM + (size_t)col0 * H_DIM),
        (const char*)(g_w2t_lo + (size_t)e * M_DIM * H_DIM + (size_t)col0 * H_DIM),
        (size_t)H_DIM * 2, H_DIM / KCHUNK, smem, acc);

    const int wm = (wid & 3) * 32;
    const int wn = (wid >> 2) * 32;
    const float* b2g = b2 + (size_t)e * M_DIM;

#pragma unroll
    for (int ni = 0; ni < 4; ++ni) {
        const int cg = col0 + wn + ni * 8 + (lane & 3) * 2;
        const float bv0 = b2g[cg], bv1 = b2g[cg + 1];
#pragma unroll
        for (int mi = 0; mi < 2; ++mi)
#pragma unroll
            for (int h = 0; h < 2; ++h) {
                const int rg = row0 + wm + mi * 16 + (lane >> 2) + h * 8;
                const int t = g_s2t[rg];
                if (t < 0) continue;
                const float g = g_gate1[t];
                float2 v;
                v.x = (acc[mi][ni][h * 2 + 0] + bv0) * g;
                v.y = (acc[mi][ni][h * 2 + 1] + bv1) * g;
                *(float2*)(out + (size_t)t * M_DIM + cg) = v;
            }
    }
}

// ---------------------------------------------------------------------------
// launch
// ---------------------------------------------------------------------------
extern "C" void kernel_launch(void* const* d_in, const int* in_sizes, int n_in,
                              void* d_out, int out_size)
{
    const float* x  = (const float*)d_in[0];
    const float* wg = (const float*)d_in[1];
    const float* w1 = (const float*)d_in[2];
    const float* b1 = (const float*)d_in[3];
    const float* w2 = (const float*)d_in[4];
    const float* b2 = (const float*)d_in[5];
    float* out = (float*)d_out;

    cudaFuncSetAttribute(gemm1_mma, cudaFuncAttributeMaxDynamicSharedMemorySize,
                         SMEM_BYTES);
    cudaFuncSetAttribute(gemm2_mma, cudaFuncAttributeMaxDynamicSharedMemorySize,
                         SMEM_BYTES);

    __nv_bfloat16 *w1t_hi, *w1t_lo, *w2t_hi, *w2t_lo;
    cudaGetSymbolAddress((void**)&w1t_hi, g_w1t_hi);
    cudaGetSymbolAddress((void**)&w1t_lo, g_w1t_lo);
    cudaGetSymbolAddress((void**)&w2t_hi, g_w2t_hi);
    cudaGetSymbolAddress((void**)&w2t_lo, g_w2t_lo);

    init_kernel<<<512, 256>>>(out);

    wsplit_kernel<<<dim3(H_DIM / 64, M_DIM / 64, E_NUM), 512>>>(
        w1, w1t_hi, w1t_lo, M_DIM, H_DIM);
    wsplit_kernel<<<dim3(M_DIM / 64, H_DIM / 64, E_NUM), 512>>>(
        w2, w2t_hi, w2t_lo, H_DIM, M_DIM);

    gate_kernel<<<N_TOK, 256>>>(x, wg);
    sched_kernel<<<1, 256>>>(out, (out_size > N_TOK * M_DIM) ? 1 : 0);
    disp_kernel<<<EC_SLOTS, 256>>>(x);

    gemm1_mma<<<dim3(H_DIM / 64, EC_SLOTS / 128), NTHREADS, SMEM_BYTES>>>(b1);
    gemm2_mma<<<dim3(M_DIM / 64, EC_SLOTS / 128), NTHREADS, SMEM_BYTES>>>(b2, out);
}

// round 17
// speedup vs baseline: 1.2404x; 1.2404x over previous
#include <cuda_runtime.h>
#include <cuda_bf16.h>
#include <cstdint>

// ---------------------------------------------------------------------------
// Problem constants
// ---------------------------------------------------------------------------
#define N_TOK    8192
#define M_DIM    2048
#define E_NUM    8
#define H_DIM    8192
#define C_CAP    1024
#define EC_SLOTS 8192

// GEMM tiling: block 128x128, 16 warps (4m x 4n), warp tile 32x32, K-chunk 64
#define KCHUNK   64
#define ROW_STRIDE_B  144                    // 64 bf16 (128B) + 16B pad
#define SPLIT_B  (128 * ROW_STRIDE_B)        // 18432 per split
#define STAGE_B  (4 * SPLIT_B)               // Ah, Al, Bh, Bl = 73728
#define NSTAGE   3
#define SMEM_BYTES (NSTAGE * STAGE_B)        // 221184
#define NTHREADS 512

// ---------------------------------------------------------------------------
// Scratch (device globals; no dynamic allocation allowed)
// ---------------------------------------------------------------------------
__device__ int   g_idx  [N_TOK];
__device__ float g_gate1[N_TOK];
__device__ float g_gates[N_TOK * E_NUM];
__device__ int   g_s2t  [EC_SLOTS];

__device__ __nv_bfloat16 g_disp_hi[(size_t)EC_SLOTS * M_DIM];
__device__ __nv_bfloat16 g_disp_lo[(size_t)EC_SLOTS * M_DIM];
__device__ __nv_bfloat16 g_h_hi   [(size_t)EC_SLOTS * H_DIM];
__device__ __nv_bfloat16 g_h_lo   [(size_t)EC_SLOTS * H_DIM];
// transposed bf16 weight splits: w1T [E][H][M], w2T [E][M][H]  (K contiguous)
__device__ __nv_bfloat16 g_w1t_hi[(size_t)E_NUM * H_DIM * M_DIM];
__device__ __nv_bfloat16 g_w1t_lo[(size_t)E_NUM * H_DIM * M_DIM];
__device__ __nv_bfloat16 g_w2t_hi[(size_t)E_NUM * M_DIM * H_DIM];
__device__ __nv_bfloat16 g_w2t_lo[(size_t)E_NUM * M_DIM * H_DIM];

// ---------------------------------------------------------------------------
// helpers
// ---------------------------------------------------------------------------
__device__ __forceinline__ uint32_t s2u(const void* p) {
    return (uint32_t)__cvta_generic_to_shared(p);
}
__device__ __forceinline__ void cp16(uint32_t s, const void* g) {
    asm volatile("cp.async.cg.shared.global [%0], [%1], 16;" :: "r"(s), "l"(g));
}
__device__ __forceinline__ void ldsm4(uint32_t* r, uint32_t a) {
    asm volatile("ldmatrix.sync.aligned.m8n8.x4.shared.b16 {%0,%1,%2,%3}, [%4];"
                 : "=r"(r[0]), "=r"(r[1]), "=r"(r[2]), "=r"(r[3]) : "r"(a));
}
__device__ __forceinline__ void ldsm2(uint32_t* r, uint32_t a) {
    asm volatile("ldmatrix.sync.aligned.m8n8.x2.shared.b16 {%0,%1}, [%2];"
                 : "=r"(r[0]), "=r"(r[1]) : "r"(a));
}
__device__ __forceinline__ void mmabf16(float* d, const uint32_t* a, const uint32_t* b) {
    asm volatile("mma.sync.aligned.m16n8k16.row.col.f32.bf16.bf16.f32 "
                 "{%0,%1,%2,%3}, {%4,%5,%6,%7}, {%8,%9}, {%0,%1,%2,%3};"
                 : "+f"(d[0]), "+f"(d[1]), "+f"(d[2]), "+f"(d[3])
                 : "r"(a[0]), "r"(a[1]), "r"(a[2]), "r"(a[3]),
                   "r"(b[0]), "r"(b[1]));
}
__device__ __forceinline__ void bsplit(float f, __nv_bfloat16& hi, __nv_bfloat16& lo)
{
    hi = __float2bfloat16(f);
    lo = __float2bfloat16(f - __bfloat162float(hi));
}

// ---------------------------------------------------------------------------
// init: slot table to -1, zero output
// ---------------------------------------------------------------------------
__global__ void init_kernel(float* __restrict__ out)
{
    int tid = blockIdx.x * blockDim.x + threadIdx.x;
    if (tid < EC_SLOTS) g_s2t[tid] = -1;
    float4* o4 = (float4*)out;
    const int n4 = (N_TOK * M_DIM) / 4;
    const int stride = gridDim.x * blockDim.x;
    for (int i = tid; i < n4; i += stride)
        o4[i] = make_float4(0.f, 0.f, 0.f, 0.f);
}

// ---------------------------------------------------------------------------
// gate: exact fp32 routing
// ---------------------------------------------------------------------------
__global__ __launch_bounds__(256) void gate_kernel(
    const float* __restrict__ x, const float* __restrict__ wg)
{
    __shared__ float sx[M_DIM];
    __shared__ float slog[E_NUM];

    const int tok = blockIdx.x;
    const int tid = threadIdx.x;

    const float4* xr = (const float4*)(x + (size_t)tok * M_DIM);
    float4* sx4 = (float4*)sx;
    for (int i = tid; i < M_DIM / 4; i += 256) sx4[i] = xr[i];
    __syncthreads();

    const int wid = tid >> 5, lane = tid & 31;
    const float* __restrict__ w = wg + wid * M_DIM;
    float sum = 0.f;
    for (int m = lane; m < M_DIM; m += 32) sum = fmaf(sx[m], w[m], sum);
#pragma unroll
    for (int o = 16; o; o >>= 1) sum += __shfl_xor_sync(0xffffffffu, sum, o);
    if (lane == 0) slog[wid] = sum;
    __syncthreads();

    if (tid == 0) {
        float mx = slog[0]; int am = 0;
#pragma unroll
        for (int e = 1; e < E_NUM; ++e)
            if (slog[e] > mx) { mx = slog[e]; am = e; }
        float ge[E_NUM], den = 0.f;
#pragma unroll
        for (int e = 0; e < E_NUM; ++e) { ge[e] = expf(slog[e] - mx); den += ge[e]; }
        const float inv = 1.f / den;
#pragma unroll
        for (int e = 0; e < E_NUM; ++e) g_gates[tok * E_NUM + e] = ge[e] * inv;
        g_idx[tok]   = am;
        g_gate1[tok] = ge[am] * inv;
    }
}

// ---------------------------------------------------------------------------
// sched: exact cumsum capacity assignment + l_aux
// ---------------------------------------------------------------------------
__global__ __launch_bounds__(256) void sched_kernel(float* __restrict__ out,
                                                    int write_laux)
{
    __shared__ int   s_ce[E_NUM];
    __shared__ float s_me[E_NUM];

    const int tid = threadIdx.x;
    const int wid = tid >> 5, lane = tid & 31;

    int count = 0;
    for (int base = 0; base < N_TOK; base += 32) {
        const int tok = base + lane;
        const bool mine = (g_idx[tok] == wid);
        const unsigned bal = __ballot_sync(0xffffffffu, mine);
        if (mine) {
            const int loc = count + __popc(bal & ((1u << lane) - 1u));
            if (loc < C_CAP) g_s2t[wid * C_CAP + loc] = tok;
        }
        count += __popc(bal);
    }
    if (lane == 0) s_ce[wid] = count;

    float me = 0.f;
    for (int t = lane; t < N_TOK; t += 32) me += g_gates[t * E_NUM + wid];
#pragma unroll
    for (int o = 16; o; o >>= 1) me += __shfl_xor_sync(0xffffffffu, me, o);
    if (lane == 0) s_me[wid] = me;
    __syncthreads();

    if (tid == 0 && write_laux) {
        float acc = 0.f;
#pragma unroll
        for (int e = 0; e < E_NUM; ++e) acc += s_me[e] * (float)s_ce[e];
        out[(size_t)N_TOK * M_DIM] =
            acc * ((float)E_NUM / ((float)N_TOK * (float)N_TOK));
    }
}

// ---------------------------------------------------------------------------
// disp: gather token rows into slot order, split fp32 -> bf16 hi/lo
// ---------------------------------------------------------------------------
__global__ __launch_bounds__(256) void disp_kernel(const float* __restrict__ x)
{
    const int slot = blockIdx.x;
    const int t = g_s2t[slot];
    const float4* src = (t >= 0) ? (const float4*)(x + (size_t)t * M_DIM) : nullptr;
    __nv_bfloat16* dh = g_disp_hi + (size_t)slot * M_DIM;
    __nv_bfloat16* dl = g_disp_lo + (size_t)slot * M_DIM;
    for (int i = threadIdx.x; i < M_DIM / 4; i += 256) {
        float4 v = src ? src[i] : make_float4(0.f, 0.f, 0.f, 0.f);
        __nv_bfloat16 hh[4], ll[4];
        bsplit(v.x, hh[0], ll[0]); bsplit(v.y, hh[1], ll[1]);
        bsplit(v.z, hh[2], ll[2]); bsplit(v.w, hh[3], ll[3]);
        *(uint2*)(dh + i * 4) = *(uint2*)hh;
        *(uint2*)(dl + i * 4) = *(uint2*)ll;
    }
}

// ---------------------------------------------------------------------------
// wsplit v2: 64x64 tiles, vectorized, amortized index math
// ---------------------------------------------------------------------------
__global__ __launch_bounds__(512) void wsplit_kernel(
    const float* __restrict__ src,
    __nv_bfloat16* __restrict__ dhi,
    __nv_bfloat16* __restrict__ dlo,
    int R, int C)
{
    __shared__ float tile[64][65];
    const int e  = blockIdx.z;
    const int c0 = blockIdx.x * 64;
    const int r0 = blockIdx.y * 64;
    const int tid = threadIdx.x;

    const float* s = src + (size_t)e * R * C;
#pragma unroll
    for (int i = 0; i < 2; ++i) {
        const int u = tid + i * 512;
        const int row = u >> 4, q = u & 15;
        float4 v = *(const float4*)(s + (size_t)(r0 + row) * C + c0 + q * 4);
        tile[row][q * 4 + 0] = v.x;
        tile[row][q * 4 + 1] = v.y;
        tile[row][q * 4 + 2] = v.z;
        tile[row][q * 4 + 3] = v.w;
    }
    __syncthreads();

    const int c  = tid >> 3;
    const int rg = tid & 7;
    __nv_bfloat16 hh[8], ll[8];
#pragma unroll
    for (int j = 0; j < 8; ++j)
        bsplit(tile[rg * 8 + j][c], hh[j], ll[j]);
    const size_t o = (size_t)e * C * R + (size_t)(c0 + c) * R + r0 + rg * 8;
    *(uint4*)(dhi + o) = *(uint4*)hh;
    *(uint4*)(dlo + o) = *(uint4*)ll;
}

// ---------------------------------------------------------------------------
// HMMA mainloop: 128x128 block, 16 warps, 3-term bf16 split,
// K-chunk 64 (half the barriers of KCHUNK=32), 3-stage cp.async pipeline
// ---------------------------------------------------------------------------
__device__ __forceinline__ void hmma_mainloop(
    const char* __restrict__ Ah, const char* __restrict__ Al,
    const char* __restrict__ Bh, const char* __restrict__ Bl,
    size_t pitch, int chunks, char* smem, float acc[2][4][4])
{
    const int tid  = threadIdx.x;
    const int wid  = tid >> 5, lane = tid & 31;
    const int wm   = (wid & 3) * 32;
    const int wn   = (wid >> 2) * 32;
    const uint32_t sbase = s2u(smem);

    // loader: per plane 128 rows x 8 segs = 1024 units; 2 units/thread/plane
    const int r0l = tid >> 3, s0l = tid & 7;             // unit tid
    const int r1l = (tid + 512) >> 3, s1l = (tid + 512) & 7;
    const uint32_t so0 = r0l * ROW_STRIDE_B + s0l * 16;
    const uint32_t so1 = r1l * ROW_STRIDE_B + s1l * 16;
    const size_t go0 = (size_t)r0l * pitch + s0l * 16;
    const size_t go1 = (size_t)r1l * pitch + s1l * 16;

    auto load_stage = [&](int st, int c) {
        const uint32_t sb = sbase + st * STAGE_B;
        const size_t kb = (size_t)c * (KCHUNK * 2);
        cp16(sb + 0 * SPLIT_B + so0, Ah + go0 + kb);
        cp16(sb + 0 * SPLIT_B + so1, Ah + go1 + kb);
        cp16(sb + 1 * SPLIT_B + so0, Al + go0 + kb);
        cp16(sb + 1 * SPLIT_B + so1, Al + go1 + kb);
        cp16(sb + 2 * SPLIT_B + so0, Bh + go0 + kb);
        cp16(sb + 2 * SPLIT_B + so1, Bh + go1 + kb);
        cp16(sb + 3 * SPLIT_B + so0, Bl + go0 + kb);
        cp16(sb + 3 * SPLIT_B + so1, Bl + go1 + kb);
        asm volatile("cp.async.commit_group;");
    };

#pragma unroll
    for (int s = 0; s < NSTAGE - 1; ++s) load_stage(s, s);

    const uint32_t aoff = (uint32_t)((wm + (lane & 15)) * ROW_STRIDE_B
                                     + ((lane >> 4) & 1) * 16);
    const uint32_t boff = (uint32_t)((wn + (lane & 7)) * ROW_STRIDE_B
                                     + ((lane >> 3) & 1) * 16);

    int buf = 0;
#pragma unroll 1
    for (int c = 0; c < chunks; ++c) {
        asm volatile("cp.async.wait_group %0;" :: "n"(NSTAGE - 2) : "memory");
        __syncthreads();

        if (c + NSTAGE - 1 < chunks)
            load_stage((c + NSTAGE - 1) % NSTAGE, c + NSTAGE - 1);

        const uint32_t sb = sbase + buf * STAGE_B;
#pragma unroll
        for (int ks = 0; ks < 4; ++ks) {
            const int kb2 = ks * 32;             // 16 elems * 2 bytes
            uint32_t ah[2][4], al[2][4], bh[4][2], bl[4][2];
#pragma unroll
            for (int mi = 0; mi < 2; ++mi) {
                const uint32_t ad = sb + aoff + kb2 + mi * 16 * ROW_STRIDE_B;
                ldsm4(ah[mi], ad);
                ldsm4(al[mi], ad + SPLIT_B);
            }
#pragma unroll
            for (int ni = 0; ni < 4; ++ni) {
                const uint32_t bd = sb + 2 * SPLIT_B + boff + kb2
                                    + ni * 8 * ROW_STRIDE_B;
                ldsm2(bh[ni], bd);
                ldsm2(bl[ni], bd + SPLIT_B);
            }
#pragma unroll
            for (int mi = 0; mi < 2; ++mi)
#pragma unroll
                for (int ni = 0; ni < 4; ++ni)
                    mmabf16(acc[mi][ni], ah[mi], bh[ni]);
#pragma unroll
            for (int mi = 0; mi < 2; ++mi)
#pragma unroll
                for (int ni = 0; ni < 4; ++ni)
                    mmabf16(acc[mi][ni], al[mi], bh[ni]);
#pragma unroll
            for (int mi = 0; mi < 2; ++mi)
#pragma unroll
                for (int ni = 0; ni < 4; ++ni)
                    mmabf16(acc[mi][ni], ah[mi], bl[ni]);
        }
        buf = (buf + 1 == NSTAGE) ? 0 : buf + 1;
    }
}

// ---------------------------------------------------------------------------
// GEMM1: h[slot] = relu( disp[slot] @ w1[e]^T(cols) + b1[e] ) -> split hi/lo
// ---------------------------------------------------------------------------
__global__ __launch_bounds__(NTHREADS, 1) void gemm1_mma(const float* __restrict__ b1)
{
    extern __shared__ char smem[];
    const int tid = threadIdx.x;
    const int wid = tid >> 5, lane = tid & 31;
    const int row0 = blockIdx.y * 128;
    const int col0 = blockIdx.x * 128;
    const int e    = row0 >> 10;

    float acc[2][4][4];
#pragma unroll
    for (int mi = 0; mi < 2; ++mi)
#pragma unroll
        for (int ni = 0; ni < 4; ++ni)
#pragma unroll
            for (int k = 0; k < 4; ++k) acc[mi][ni][k] = 0.f;

    hmma_mainloop(
        (const char*)(g_disp_hi + (size_t)row0 * M_DIM),
        (const char*)(g_disp_lo + (size_t)row0 * M_DIM),
        (const char*)(g_w1t_hi + (size_t)e * H_DIM * M_DIM + (size_t)col0 * M_DIM),
        (const char*)(g_w1t_lo + (size_t)e * H_DIM * M_DIM + (size_t)col0 * M_DIM),
        (size_t)M_DIM * 2, M_DIM / KCHUNK, smem, acc);

    const int wm = (wid & 3) * 32;
    const int wn = (wid >> 2) * 32;
    const float* b1g = b1 + (size_t)e * H_DIM;

#pragma unroll
    for (int ni = 0; ni < 4; ++ni) {
        const int cg = col0 + wn + ni * 8 + (lane & 3) * 2;
        const float bv0 = b1g[cg], bv1 = b1g[cg + 1];
#pragma unroll
        for (int mi = 0; mi < 2; ++mi)
#pragma unroll
            for (int h = 0; h < 2; ++h) {
                const int rg = row0 + wm + mi * 16 + (lane >> 2) + h * 8;
                float v0 = fmaxf(acc[mi][ni][h * 2 + 0] + bv0, 0.f);
                float v1 = fmaxf(acc[mi][ni][h * 2 + 1] + bv1, 0.f);
                __nv_bfloat16 h0, l0, h1, l1;
                bsplit(v0, h0, l0);
                bsplit(v1, h1, l1);
                *(__nv_bfloat162*)(g_h_hi + (size_t)rg * H_DIM + cg) =
                    __nv_bfloat162(h0, h1);
                *(__nv_bfloat162*)(g_h_lo + (size_t)rg * H_DIM + cg) =
                    __nv_bfloat162(l0, l1);
            }
    }
}

// ---------------------------------------------------------------------------
// GEMM2: out[token(slot)] = gate1 * ( h[slot] @ w2[e]^T(cols) + b2[e] )
// ---------------------------------------------------------------------------
__global__ __launch_bounds__(NTHREADS, 1) void gemm2_mma(const float* __restrict__ b2,
                                                         float* __restrict__ out)
{
    extern __shared__ char smem[];
    const int tid = threadIdx.x;
    const int wid = tid >> 5, lane = tid & 31;
    const int row0 = blockIdx.y * 128;
    const int col0 = blockIdx.x * 128;
    const int e    = row0 >> 10;

    float acc[2][4][4];
#pragma unroll
    for (int mi = 0; mi < 2; ++mi)
#pragma unroll
        for (int ni = 0; ni < 4; ++ni)
#pragma unroll
            for (int k = 0; k < 4; ++k) acc[mi][ni][k] = 0.f;

    hmma_mainloop(
        (const char*)(g_h_hi + (size_t)row0 * H_DIM),
        (const char*)(g_h_lo + (size_t)row0 * H_DIM),
        (const char*)(g_w2t_hi + (size_t)e * M_DIM * H_DIM + (size_t)col0 * H_DIM),
        (const char*)(g_w2t_lo + (size_t)e * M_DIM * H_DIM + (size_t)col0 * H_DIM),
        (size_t)H_DIM * 2, H_DIM / KCHUNK, smem, acc);

    const int wm = (wid & 3) * 32;
    const int wn = (wid >> 2) * 32;
    const float* b2g = b2 + (size_t)e * M_DIM;

#pragma unroll
    for (int ni = 0; ni < 4; ++ni) {
        const int cg = col0 + wn + ni * 8 + (lane & 3) * 2;
        const float bv0 = b2g[cg], bv1 = b2g[cg + 1];
#pragma unroll
        for (int mi = 0; mi < 2; ++mi)
#pragma unroll
            for (int h = 0; h < 2; ++h) {
                const int rg = row0 + wm + mi * 16 + (lane >> 2) + h * 8;
                const int t = g_s2t[rg];
                if (t < 0) continue;
                const float g = g_gate1[t];
                float2 v;
                v.x = (acc[mi][ni][h * 2 + 0] + bv0) * g;
                v.y = (acc[mi][ni][h * 2 + 1] + bv1) * g;
                *(float2*)(out + (size_t)t * M_DIM + cg) = v;
            }
    }
}

// ---------------------------------------------------------------------------
// launch
// ---------------------------------------------------------------------------
extern "C" void kernel_launch(void* const* d_in, const int* in_sizes, int n_in,
                              void* d_out, int out_size)
{
    const float* x  = (const float*)d_in[0];
    const float* wg = (const float*)d_in[1];
    const float* w1 = (const float*)d_in[2];
    const float* b1 = (const float*)d_in[3];
    const float* w2 = (const float*)d_in[4];
    const float* b2 = (const float*)d_in[5];
    float* out = (float*)d_out;

    cudaFuncSetAttribute(gemm1_mma, cudaFuncAttributeMaxDynamicSharedMemorySize,
                         SMEM_BYTES);
    cudaFuncSetAttribute(gemm2_mma, cudaFuncAttributeMaxDynamicSharedMemorySize,
                         SMEM_BYTES);

    __nv_bfloat16 *w1t_hi, *w1t_lo, *w2t_hi, *w2t_lo;
    cudaGetSymbolAddress((void**)&w1t_hi, g_w1t_hi);
    cudaGetSymbolAddress((void**)&w1t_lo, g_w1t_lo);
    cudaGetSymbolAddress((void**)&w2t_hi, g_w2t_hi);
    cudaGetSymbolAddress((void**)&w2t_lo, g_w2t_lo);

    init_kernel<<<512, 256>>>(out);

    wsplit_kernel<<<dim3(H_DIM / 64, M_DIM / 64, E_NUM), 512>>>(
        w1, w1t_hi, w1t_lo, M_DIM, H_DIM);
    wsplit_kernel<<<dim3(M_DIM / 64, H_DIM / 64, E_NUM), 512>>>(
        w2, w2t_hi, w2t_lo, H_DIM, M_DIM);

    gate_kernel<<<N_TOK, 256>>>(x, wg);
    sched_kernel<<<1, 256>>>(out, (out_size > N_TOK * M_DIM) ? 1 : 0);
    disp_kernel<<<EC_SLOTS, 256>>>(x);

    gemm1_mma<<<dim3(H_DIM / 128, EC_SLOTS / 128), NTHREADS, SMEM_BYTES>>>(b1);
    gemm2_mma<<<dim3(M_DIM / 128, EC_SLOTS / 128), NTHREADS, SMEM_BYTES>>>(b2, out);
}